// round 6
// baseline (speedup 1.0000x reference)
#include <cuda_runtime.h>
#include <cstdint>

// SpatialTransformer bilinear flow warp — smem-staged tile version.
// src:  [B,H,W,1] f32,  flow: [B,H,W,2] f32,  out: [B,H,W,1] f32
// B=32, H=768, W=768.
//
// R5 analysis: per-lane y-displacement makes the 4 global gathers per warp
// touch ~6x the cache lines of a coalesced load -> L1tex wavefronts bind.
// Fix: stage a (64+34)x(32+34) src tile in smem via coalesced loads, gather
// from LDS (29cyc, conflict-light). Pixels whose (clipped) corner indices
// fall outside the staged window (|flow|>~16, a 5.3-sigma event) fall back
// to global gathers -> bit-identical results.

#define BB 32
#define HH 768
#define WW 768
#define HW (HH * WW)

#define TX 64            // tile width (pixels)
#define TY 32            // tile height (pixels)
#define HALO_LO 16
#define HALO_HI 18       // +1 for x1/y1 corner, +1 slack
#define SW (TX + HALO_LO + HALO_HI)   // 98
#define SH (TY + HALO_LO + HALO_HI)   // 66
#define SSTRIDE 99       // 99 mod 32 = 3 -> adjacent rows shift banks

__global__ __launch_bounds__(256) void warp_kernel(
    const float* __restrict__ src,
    const float* __restrict__ flow,
    float* __restrict__ out)
{
    __shared__ float tile[SH * SSTRIDE];   // 66*99*4 = 26136 B

    const int tid = threadIdx.x;
    const int b   = blockIdx.z;
    const int xs  = blockIdx.x * TX - HALO_LO;   // tile origin (may be <0)
    const int ys  = blockIdx.y * TY - HALO_LO;

    const float* img = src + b * HW;

    // ---- stage src tile (+halo) into smem, coalesced, edge-clamped ----
    #pragma unroll 4
    for (int i = tid; i < SH * SW; i += 256) {
        const int row = i / SW;
        const int col = i - row * SW;
        const int gy  = min(max(ys + row, 0), HH - 1);
        const int gx  = min(max(xs + col, 0), WW - 1);
        tile[row * SSTRIDE + col] = __ldg(img + gy * WW + gx);
    }
    __syncthreads();

    // ---- per-pixel compute: warp = 32 consecutive x, 8-row strip/warp ----
    const int wid  = tid >> 5;
    const int lane = tid & 31;
    const int xg   = blockIdx.x * TX + (wid & 1) * 32 + lane;
    const int yb   = blockIdx.y * TY + (wid >> 1) * 8;
    const float xgf = (float)xg;

    #pragma unroll
    for (int r = 0; r < 8; r++) {
        const int y   = yb + r;
        const int pix = (b * HH + y) * WW + xg;

        const float2 f = *reinterpret_cast<const float2*>(flow + (size_t)pix * 2);

        const float gx = xgf + f.x;
        const float gy = (float)y + f.y;

        const float x0f = floorf(gx);
        const float y0f = floorf(gy);
        const float x1f = x0f + 1.0f;
        const float y1f = y0f + 1.0f;

        // weights from UNCLIPPED corners (matches reference)
        const float dx1 = x1f - gx;
        const float dx0 = gx - x0f;
        const float dy1 = y1f - gy;
        const float dy0 = gy - y0f;

        const float wa = dx1 * dy1;
        const float wb = dx0 * dy1;
        const float wc = dx1 * dy0;
        const float wd = dx0 * dy0;

        // clipped integer indices
        const int xi0 = (int)fminf(fmaxf(x0f, 0.0f), (float)(WW - 1));
        const int xi1 = (int)fminf(fmaxf(x1f, 0.0f), (float)(WW - 1));
        const int yi0 = (int)fminf(fmaxf(y0f, 0.0f), (float)(HH - 1));
        const int yi1 = (int)fminf(fmaxf(y1f, 0.0f), (float)(HH - 1));

        float va, vb, vc, vd;
        const bool inb = (xi0 >= xs) & (xi1 < xs + SW) &
                         (yi0 >= ys) & (yi1 < ys + SH);
        if (inb) {
            const int r0 = (yi0 - ys) * SSTRIDE - xs;   // add xi to index
            const int r1 = (yi1 - ys) * SSTRIDE - xs;
            va = tile[r0 + xi0];
            vb = tile[r0 + xi1];
            vc = tile[r1 + xi0];
            vd = tile[r1 + xi1];
        } else {                     // ~5-sigma flow outlier: exact fallback
            const int g0 = yi0 * WW;
            const int g1 = yi1 * WW;
            va = __ldg(img + g0 + xi0);
            vb = __ldg(img + g0 + xi1);
            vc = __ldg(img + g1 + xi0);
            vd = __ldg(img + g1 + xi1);
        }

        out[pix] = wa * va + wb * vb + wc * vc + wd * vd;
    }
}

extern "C" void kernel_launch(void* const* d_in, const int* in_sizes, int n_in,
                              void* d_out, int out_size)
{
    const float* src  = (const float*)d_in[0];
    const float* flow = (const float*)d_in[1];
    float* out = (float*)d_out;

    dim3 grid(WW / TX, HH / TY, BB);   // (12, 24, 32)
    warp_kernel<<<grid, 256>>>(src, flow, out);
}

// round 7
// speedup vs baseline: 1.2124x; 1.2124x over previous
#include <cuda_runtime.h>
#include <cstdint>

// SpatialTransformer bilinear flow warp — low-overhead smem-staged tile.
// src:  [B,H,W,1] f32,  flow: [B,H,W,2] f32,  out: [B,H,W,1] f32
// B=32, H=768, W=768.
//
// R6 showed smem staging kills L1tex gather wavefronts (L1 70->55%) but its
// div/mod scalar staging loop made the kernel issue-bound (75.6%, ALU 52%).
// This version removes the instruction tax:
//   - tile stride 128 floats (pow-2: shift/mask indexing only)
//   - interior blocks stage via float4 (6 iters of LDG.128+STS.128)
//   - border blocks use the clamped scalar path
//   - 384-thread blocks, 5 blocks/SM -> 60 warps (94% occ), 32KB smem each
// Pixels whose clipped corners fall outside the staged window (|flow|>15,
// ~5 sigma) use exact global-gather fallback -> bit-identical results.

#define BB 32
#define HH 768
#define WW 768
#define HW (HH * WW)

#define TX 96
#define TY 32
#define HALO 16
#define SW 128           // TX + 2*HALO = 128 (pow-2 stride)
#define SH 64            // TY + 2*HALO

__global__ __launch_bounds__(384, 5) void warp_kernel(
    const float* __restrict__ src,
    const float* __restrict__ flow,
    float* __restrict__ out)
{
    __shared__ float tile[SH * SW];    // 64*128*4 = 32768 B

    const int tid = threadIdx.x;
    const int b   = blockIdx.z;
    const int xs  = blockIdx.x * TX - HALO;   // tile origin
    const int ys  = blockIdx.y * TY - HALO;

    const float* img = src + b * HW;

    // ---- stage src tile (+halo) into smem ----
    if (xs >= 0 && xs + SW <= WW && ys >= 0 && ys + SH <= HH) {
        // interior: fully in-range, 16B-aligned (xs = 96*bx-16 is mult of 16)
        const float* srcb = img + ys * WW + xs;
        #pragma unroll
        for (int k = 0; k < 6; k++) {
            const int i = tid + k * 384;      // float4 index, need i < 2048
            if (i < (SH * SW) / 4) {
                const int row = i >> 5;           // 32 float4 per row
                const int c4  = (i & 31) << 2;
                *reinterpret_cast<float4*>(tile + row * SW + c4) =
                    *reinterpret_cast<const float4*>(srcb + row * WW + c4);
            }
        }
    } else {
        // border: clamped scalar staging
        for (int i = tid; i < SH * SW; i += 384) {
            const int row = i >> 7;
            const int col = i & 127;
            const int gy  = min(max(ys + row, 0), HH - 1);
            const int gx  = min(max(xs + col, 0), WW - 1);
            tile[i] = __ldg(img + gy * WW + gx);
        }
    }
    __syncthreads();

    // ---- consumer: warp = 32 consecutive x, 8-row strip per warp ----
    const int wid  = tid >> 5;          // 0..11
    const int lane = tid & 31;
    const int xg   = blockIdx.x * TX + (wid % 3) * 32 + lane;
    const int yb   = blockIdx.y * TY + (wid / 3) * 8;
    const float xgf = (float)xg;

    #pragma unroll
    for (int r = 0; r < 8; r++) {
        const int y   = yb + r;
        const int pix = (b * HH + y) * WW + xg;

        const float2 f = *reinterpret_cast<const float2*>(flow + (size_t)pix * 2);

        const float gx = xgf + f.x;
        const float gy = (float)y + f.y;

        const float x0f = floorf(gx);
        const float y0f = floorf(gy);
        const float x1f = x0f + 1.0f;
        const float y1f = y0f + 1.0f;

        // weights from UNCLIPPED corners (matches reference)
        const float dx1 = x1f - gx;
        const float dx0 = gx - x0f;
        const float dy1 = y1f - gy;
        const float dy0 = gy - y0f;

        const float wa = dx1 * dy1;
        const float wb = dx0 * dy1;
        const float wc = dx1 * dy0;
        const float wd = dx0 * dy0;

        // clipped integer indices
        const int xi0 = (int)fminf(fmaxf(x0f, 0.0f), (float)(WW - 1));
        const int xi1 = (int)fminf(fmaxf(x1f, 0.0f), (float)(WW - 1));
        const int yi0 = (int)fminf(fmaxf(y0f, 0.0f), (float)(HH - 1));
        const int yi1 = (int)fminf(fmaxf(y1f, 0.0f), (float)(HH - 1));

        float va, vb, vc, vd;
        const bool inb = (xi0 >= xs) & (xi1 < xs + SW) &
                         (yi0 >= ys) & (yi1 < ys + SH);
        if (inb) {
            const int r0 = (yi0 - ys) * SW - xs;
            const int r1 = (yi1 - ys) * SW - xs;
            va = tile[r0 + xi0];
            vb = tile[r0 + xi1];
            vc = tile[r1 + xi0];
            vd = tile[r1 + xi1];
        } else {                     // ~5-sigma flow outlier: exact fallback
            const int g0 = yi0 * WW;
            const int g1 = yi1 * WW;
            va = __ldg(img + g0 + xi0);
            vb = __ldg(img + g0 + xi1);
            vc = __ldg(img + g1 + xi0);
            vd = __ldg(img + g1 + xi1);
        }

        out[pix] = wa * va + wb * vb + wc * vc + wd * vd;
    }
}

extern "C" void kernel_launch(void* const* d_in, const int* in_sizes, int n_in,
                              void* d_out, int out_size)
{
    const float* src  = (const float*)d_in[0];
    const float* flow = (const float*)d_in[1];
    float* out = (float*)d_out;

    dim3 grid(WW / TX, HH / TY, BB);   // (8, 24, 32)
    warp_kernel<<<grid, 384>>>(src, flow, out);
}

// round 8
// speedup vs baseline: 1.3902x; 1.1466x over previous
#include <cuda_runtime.h>
#include <cstdint>

// SpatialTransformer bilinear flow warp — R5 layout + clamp-free fast path.
// src:  [B,H,W,1] f32,  flow: [B,H,W,2] f32,  out: [B,H,W,1] f32
// B=32, H=768, W=768.
//
// Layout (proven best): 32x16 tile / 128-thread block; lane -> 32 consecutive
// x (coalesced), warp -> 4-row strip (L1 halo reuse). 32 regs, ~88% occ.
//
// New: per-pixel fast path. If floor corners are naturally in [0, dim-2],
// the reference's clamps are identity, so we skip 8 FMNMX + 2 F2I + 4 IADD
// and fold the +1/+W corner offsets into LDG immediate offsets. Border /
// outlier pixels (~2%) take the exact reference slow path. Bit-identical.

#define BB 32
#define HH 768
#define WW 768
#define HW (HH * WW)

__global__ __launch_bounds__(128) void warp_kernel(
    const float* __restrict__ src,
    const float* __restrict__ flow,
    float* __restrict__ out)
{
    const int tx = threadIdx.x;
    const int xg = blockIdx.x * 32 + (tx & 31);       // global x
    const int yb = blockIdx.y * 16 + (tx >> 5) * 4;   // first of 4 rows
    const int b  = blockIdx.z;

    const float* img = src + b * HW;
    const float  xgf = (float)xg;

    #pragma unroll
    for (int r = 0; r < 4; r++) {
        const int y   = yb + r;
        const int pix = (b * HH + y) * WW + xg;

        const float2 f = *reinterpret_cast<const float2*>(flow + (size_t)pix * 2);

        const float gx = xgf + f.x;
        const float gy = (float)y + f.y;

        const float x0f = floorf(gx);
        const float y0f = floorf(gy);
        const float x1f = x0f + 1.0f;
        const float y1f = y0f + 1.0f;

        // weights from UNCLIPPED corners — exact reference formulation
        const float dx1 = x1f - gx;
        const float dx0 = gx - x0f;
        const float dy1 = y1f - gy;
        const float dy0 = gy - y0f;

        const float wa = dx1 * dy1;
        const float wb = dx0 * dy1;
        const float wc = dx1 * dy0;
        const float wd = dx0 * dy0;

        const int ix0 = (int)x0f;    // saturating F2I; guard rejects junk
        const int iy0 = (int)y0f;

        float va, vb, vc, vd;
        // fast iff ix0 in [0, W-2] and iy0 in [0, H-2]: clamps are identity
        if (((unsigned)ix0 < (WW - 1)) & ((unsigned)iy0 < (HH - 1))) {
            const float* p = img + iy0 * WW + ix0;
            va = __ldg(p);
            vb = __ldg(p + 1);
            vc = __ldg(p + WW);
            vd = __ldg(p + WW + 1);
        } else {
            // exact reference slow path (clamped indices)
            const int xi0 = (int)fminf(fmaxf(x0f, 0.0f), (float)(WW - 1));
            const int xi1 = (int)fminf(fmaxf(x1f, 0.0f), (float)(WW - 1));
            const int yi0 = (int)fminf(fmaxf(y0f, 0.0f), (float)(HH - 1));
            const int yi1 = (int)fminf(fmaxf(y1f, 0.0f), (float)(HH - 1));
            const int g0 = yi0 * WW;
            const int g1 = yi1 * WW;
            va = __ldg(img + g0 + xi0);
            vb = __ldg(img + g0 + xi1);
            vc = __ldg(img + g1 + xi0);
            vd = __ldg(img + g1 + xi1);
        }

        out[pix] = wa * va + wb * vb + wc * vc + wd * vd;
    }
}

extern "C" void kernel_launch(void* const* d_in, const int* in_sizes, int n_in,
                              void* d_out, int out_size)
{
    const float* src  = (const float*)d_in[0];
    const float* flow = (const float*)d_in[1];
    float* out = (float*)d_out;

    dim3 grid(WW / 32, HH / 16, BB);   // (24, 48, 32)
    warp_kernel<<<grid, 128>>>(src, flow, out);
}